// round 10
// baseline (speedup 1.0000x reference)
#include <cuda_runtime.h>
#include <cstdint>

// Fused coefficients: [ka0, kc0, ka1, kc1, bias]
__device__ float g_coef[5];

#define LAYERS 8
#define N_QUBITS 16
#define THREADS 256
#define ROW_BYTES 64                      // 16 floats per row
#define CHUNK_BYTES (THREADS * ROW_BYTES) // 16 KB per block

__device__ __forceinline__ uint32_t smem_u32(const void* p) {
    uint32_t a;
    asm("{ .reg .u64 t; cvta.to.shared.u64 t, %1; cvt.u32.u64 %0, t; }"
        : "=r"(a) : "l"(p));
    return a;
}

// Thread q (q=0,1) composes the 8-layer Rot chain for qubit q into one 2x2
// complex unitary, reduces it to the (A, C) pair of the closed form
//   ez(x) = A*cos(x) - C*sin(x),  and folds in the linear head.
__global__ void vqc_precompute_kernel(const float* __restrict__ params,
                                      const float* __restrict__ head_w,
                                      const float* __restrict__ head_b) {
    int q = threadIdx.x;
    if (q >= 2) return;

    float u00r = 1.f, u00i = 0.f, u01r = 0.f, u01i = 0.f;
    float u10r = 0.f, u10i = 0.f, u11r = 1.f, u11i = 0.f;

    #pragma unroll
    for (int l = 0; l < LAYERS; l++) {
        float phi   = params[l * (N_QUBITS * 3) + q * 3 + 0];
        float theta = params[l * (N_QUBITS * 3) + q * 3 + 1];
        float omega = params[l * (N_QUBITS * 3) + q * 3 + 2];
        float ct, st, cp, sp, cm, sm;
        __sincosf(0.5f * theta, &st, &ct);
        __sincosf(-0.5f * (phi + omega), &sp, &cp);
        __sincosf(0.5f * (phi - omega), &sm, &cm);
        float m00r =  cp * ct, m00i =  sp * ct;
        float m01r = -cm * st, m01i = -sm * st;
        float m10r =  cm * st, m10i = -sm * st;
        float m11r =  cp * ct, m11i = -sp * ct;

        float n00r = m00r*u00r - m00i*u00i + m01r*u10r - m01i*u10i;
        float n00i = m00r*u00i + m00i*u00r + m01r*u10i + m01i*u10r;
        float n01r = m00r*u01r - m00i*u01i + m01r*u11r - m01i*u11i;
        float n01i = m00r*u01i + m00i*u01r + m01r*u11i + m01i*u11r;
        float n10r = m10r*u00r - m10i*u00i + m11r*u10r - m11i*u10i;
        float n10i = m10r*u00i + m10i*u00r + m11r*u10i + m11i*u10r;
        float n11r = m10r*u01r - m10i*u01i + m11r*u11r - m11i*u11i;
        float n11i = m10r*u01i + m10i*u01r + m11r*u11i + m11i*u11r;
        u00r = n00r; u00i = n00i; u01r = n01r; u01i = n01i;
        u10r = n10r; u10i = n10i; u11r = n11r; u11i = n11i;
    }

    float A = (u00r*u00r + u00i*u00i) - (u10r*u10r + u10i*u10i);
    float C = (u00i*u01r - u00r*u01i) - (u10i*u11r - u10r*u11i);

    float w = head_w[q];
    g_coef[q * 2 + 0] = w * A;
    g_coef[q * 2 + 1] = w * C;
    if (q == 0) g_coef[4] = head_b[0];
}

// TMA-path streaming kernel: each block bulk-copies its 256-row (16 KB)
// contiguous chunk of X into SMEM with one cp.async.bulk (UBLKCP). Bulk-copy
// misses are tracked by the TMA engine, not the per-SM L1 MSHR pool that
// capped every LDG-based variant at ~3.5-3.9 TB/s. Threads then read their
// 8-byte row prefix from SMEM, evaluate the closed form, and store.
//
// Fixed vs R9: __syncthreads() between mbarrier.init and any try_wait —
// waiting on an uninitialized mbarrier is UB (caused the launch failure).
__global__ void __launch_bounds__(THREADS)
vqc_main_kernel(const float* __restrict__ X, float* __restrict__ out, int B) {
    __shared__ alignas(128) char buf[CHUNK_BYTES];
    __shared__ alignas(8) unsigned long long mbar;

    int base = blockIdx.x * THREADS;
    int rows = B - base;
    if (rows <= 0) return;
    if (rows > THREADS) rows = THREADS;
    unsigned bytes = (unsigned)rows * ROW_BYTES;

    uint32_t mbar_a = smem_u32(&mbar);
    uint32_t buf_a  = smem_u32(buf);

    if (threadIdx.x == 0) {
        asm volatile("mbarrier.init.shared::cta.b64 [%0], 1;"
                     :: "r"(mbar_a) : "memory");
        asm volatile("fence.proxy.async.shared::cta;" ::: "memory");
    }
    __syncthreads();   // init visible to ALL threads before any wait

    if (threadIdx.x == 0) {
        asm volatile("mbarrier.arrive.expect_tx.shared::cta.b64 _, [%0], %1;"
                     :: "r"(mbar_a), "r"(bytes) : "memory");
        const char* src = (const char*)(X + (size_t)base * N_QUBITS);
        asm volatile(
            "cp.async.bulk.shared::cta.global.mbarrier::complete_tx::bytes "
            "[%0], [%1], %2, [%3];"
            :: "r"(buf_a), "l"(src), "r"(bytes), "r"(mbar_a) : "memory");
    }

    // all threads wait for the bulk copy (phase 0)
    {
        uint32_t done;
        asm volatile(
            "{\n\t"
            ".reg .pred p;\n\t"
            "mbarrier.try_wait.parity.acquire.cta.shared::cta.b64 p, [%1], 0;\n\t"
            "selp.b32 %0, 1, 0, p;\n\t"
            "}" : "=r"(done) : "r"(mbar_a) : "memory");
        if (!done) {
            asm volatile(
                "{\n\t"
                ".reg .pred P1;\n\t"
                "W_%=:\n\t"
                "mbarrier.try_wait.parity.acquire.cta.shared::cta.b64 P1, [%0], 0, 0x989680;\n\t"
                "@P1 bra.uni D_%=;\n\t"
                "bra.uni W_%=;\n\t"
                "D_%=:\n\t"
                "}" :: "r"(mbar_a) : "memory");
        }
    }

    if ((int)threadIdx.x < rows) {
        const float* row = (const float*)(buf + threadIdx.x * ROW_BYTES);
        float x0 = row[0];
        float x1 = row[1];

        float ka0 = g_coef[0], kc0 = g_coef[1];
        float ka1 = g_coef[2], kc1 = g_coef[3];
        float bias = g_coef[4];

        float s0, c0, s1, c1;
        __sincosf(x0, &s0, &c0);
        __sincosf(x1, &s1, &c1);

        out[base + threadIdx.x] = fmaf(ka0, c0, fmaf(-kc0, s0,
                                  fmaf(ka1, c1, fmaf(-kc1, s1, bias))));
    }
}

extern "C" void kernel_launch(void* const* d_in, const int* in_sizes, int n_in,
                              void* d_out, int out_size) {
    const float* X      = (const float*)d_in[0];   // [B, 16]
    const float* params = (const float*)d_in[1];   // [8, 16, 3]
    const float* head_w = (const float*)d_in[2];   // [1, 2]
    const float* head_b = (const float*)d_in[3];   // [1]
    float* out = (float*)d_out;

    int B = in_sizes[0] / N_QUBITS;
    int blocks = (B + THREADS - 1) / THREADS;

    vqc_precompute_kernel<<<1, 32>>>(params, head_w, head_b);
    vqc_main_kernel<<<blocks, THREADS>>>(X, out, B);
}

// round 11
// speedup vs baseline: 1.2043x; 1.2043x over previous
#include <cuda_runtime.h>

// Fused coefficients: [ka0, kc0, ka1, kc1, bias]
__device__ float g_coef[5];

#define LAYERS 8
#define N_QUBITS 16
#define THREADS 256
#define ROWS_PER_THREAD 2

// Thread q (q=0,1) composes the 8-layer Rot chain for qubit q into one 2x2
// complex unitary, reduces it to the (A, C) pair of the closed form
//   ez(x) = A*cos(x) - C*sin(x),  and folds in the linear head.
__global__ void vqc_precompute_kernel(const float* __restrict__ params,
                                      const float* __restrict__ head_w,
                                      const float* __restrict__ head_b) {
    int q = threadIdx.x;
    if (q >= 2) return;

    float u00r = 1.f, u00i = 0.f, u01r = 0.f, u01i = 0.f;
    float u10r = 0.f, u10i = 0.f, u11r = 1.f, u11i = 0.f;

    #pragma unroll
    for (int l = 0; l < LAYERS; l++) {
        float phi   = params[l * (N_QUBITS * 3) + q * 3 + 0];
        float theta = params[l * (N_QUBITS * 3) + q * 3 + 1];
        float omega = params[l * (N_QUBITS * 3) + q * 3 + 2];
        float ct, st, cp, sp, cm, sm;
        __sincosf(0.5f * theta, &st, &ct);
        __sincosf(-0.5f * (phi + omega), &sp, &cp);
        __sincosf(0.5f * (phi - omega), &sm, &cm);
        // Rot(phi,theta,omega) = RZ(omega) RY(theta) RZ(phi)
        float m00r =  cp * ct, m00i =  sp * ct;
        float m01r = -cm * st, m01i = -sm * st;
        float m10r =  cm * st, m10i = -sm * st;
        float m11r =  cp * ct, m11i = -sp * ct;

        float n00r = m00r*u00r - m00i*u00i + m01r*u10r - m01i*u10i;
        float n00i = m00r*u00i + m00i*u00r + m01r*u10i + m01i*u10r;
        float n01r = m00r*u01r - m00i*u01i + m01r*u11r - m01i*u11i;
        float n01i = m00r*u01i + m00i*u01r + m01r*u11i + m01i*u11r;
        float n10r = m10r*u00r - m10i*u00i + m11r*u10r - m11i*u10i;
        float n10i = m10r*u00i + m10i*u00r + m11r*u10i + m11i*u10r;
        float n11r = m10r*u01r - m10i*u01i + m11r*u11r - m11i*u11i;
        float n11i = m10r*u01i + m10i*u01r + m11r*u11i + m11i*u11r;
        u00r = n00r; u00i = n00i; u01r = n01r; u01i = n01i;
        u10r = n10r; u10i = n10i; u11r = n11r; u11i = n11i;
    }

    float A = (u00r*u00r + u00i*u00i) - (u10r*u10r + u10i*u10i);
    float C = (u00i*u01r - u00r*u01i) - (u10i*u11r - u10r*u11i);

    float w = head_w[q];
    g_coef[q * 2 + 0] = w * A;
    g_coef[q * 2 + 1] = w * C;
    if (q == 0) g_coef[4] = head_b[0];
}

// Single-wave streaming kernel: 2 rows per thread -> 1024 blocks x 256
// threads. 148 SMs hold 8 such blocks each (1184 capacity), so the whole
// grid is co-resident in ONE wave — no wave transition, no partial-wave
// tail (the best previous config ran 1.73 waves). Loads are front-batched
// (2 independent LDG.64 per thread), coalesced via b = tid + i*nthreads.
__global__ void __launch_bounds__(THREADS)
vqc_main_kernel(const float* __restrict__ X, float* __restrict__ out, int B) {
    int tid = blockIdx.x * blockDim.x + threadIdx.x;
    int nthreads = gridDim.x * blockDim.x;

    float x0[ROWS_PER_THREAD], x1[ROWS_PER_THREAD];

    #pragma unroll
    for (int i = 0; i < ROWS_PER_THREAD; i++) {
        int b = tid + i * nthreads;
        if (b < B) {
            const float* p = X + (size_t)b * N_QUBITS;
            asm volatile("ld.global.v2.f32 {%0, %1}, [%2];"
                         : "=f"(x0[i]), "=f"(x1[i]) : "l"(p));
        }
    }

    float ka0 = g_coef[0], kc0 = g_coef[1];
    float ka1 = g_coef[2], kc1 = g_coef[3];
    float bias = g_coef[4];

    #pragma unroll
    for (int i = 0; i < ROWS_PER_THREAD; i++) {
        int b = tid + i * nthreads;
        if (b < B) {
            float s0, c0, s1, c1;
            __sincosf(x0[i], &s0, &c0);
            __sincosf(x1[i], &s1, &c1);
            out[b] = fmaf(ka0, c0, fmaf(-kc0, s0,
                     fmaf(ka1, c1, fmaf(-kc1, s1, bias))));
        }
    }
}

extern "C" void kernel_launch(void* const* d_in, const int* in_sizes, int n_in,
                              void* d_out, int out_size) {
    const float* X      = (const float*)d_in[0];   // [B, 16]
    const float* params = (const float*)d_in[1];   // [8, 16, 3]
    const float* head_w = (const float*)d_in[2];   // [1, 2]
    const float* head_b = (const float*)d_in[3];   // [1]
    float* out = (float*)d_out;

    int B = in_sizes[0] / N_QUBITS;

    int total_threads = (B + ROWS_PER_THREAD - 1) / ROWS_PER_THREAD;
    int blocks = (total_threads + THREADS - 1) / THREADS;   // 1024 for B=524288

    vqc_precompute_kernel<<<1, 32>>>(params, head_w, head_b);
    vqc_main_kernel<<<blocks, THREADS>>>(X, out, B);
}

// round 12
// speedup vs baseline: 1.2444x; 1.0333x over previous
#include <cuda_runtime.h>

// Fused coefficients: [ka0, kc0, ka1, kc1, bias]
__device__ float g_coef[5];

#define LAYERS 8
#define N_QUBITS 16

// Thread q (q=0,1) composes the 8-layer Rot chain for qubit q into one 2x2
// complex unitary, reduces it to the (A, C) pair of the closed form
//   ez(x) = A*cos(x) - C*sin(x),  and folds in the linear head.
__global__ void vqc_precompute_kernel(const float* __restrict__ params,
                                      const float* __restrict__ head_w,
                                      const float* __restrict__ head_b) {
    int q = threadIdx.x;
    if (q >= 2) return;

    float u00r = 1.f, u00i = 0.f, u01r = 0.f, u01i = 0.f;
    float u10r = 0.f, u10i = 0.f, u11r = 1.f, u11i = 0.f;

    #pragma unroll
    for (int l = 0; l < LAYERS; l++) {
        float phi   = params[l * (N_QUBITS * 3) + q * 3 + 0];
        float theta = params[l * (N_QUBITS * 3) + q * 3 + 1];
        float omega = params[l * (N_QUBITS * 3) + q * 3 + 2];
        float ct, st, cp, sp, cm, sm;
        __sincosf(0.5f * theta, &st, &ct);
        __sincosf(-0.5f * (phi + omega), &sp, &cp);
        __sincosf(0.5f * (phi - omega), &sm, &cm);
        // Rot(phi,theta,omega) = RZ(omega) RY(theta) RZ(phi)
        float m00r =  cp * ct, m00i =  sp * ct;
        float m01r = -cm * st, m01i = -sm * st;
        float m10r =  cm * st, m10i = -sm * st;
        float m11r =  cp * ct, m11i = -sp * ct;

        float n00r = m00r*u00r - m00i*u00i + m01r*u10r - m01i*u10i;
        float n00i = m00r*u00i + m00i*u00r + m01r*u10i + m01i*u10r;
        float n01r = m00r*u01r - m00i*u01i + m01r*u11r - m01i*u11i;
        float n01i = m00r*u01i + m00i*u01r + m01r*u11i + m01i*u11r;
        float n10r = m10r*u00r - m10i*u00i + m11r*u10r - m11i*u10i;
        float n10i = m10r*u00i + m10i*u00r + m11r*u10i + m11i*u10r;
        float n11r = m10r*u01r - m10i*u01i + m11r*u11r - m11i*u11i;
        float n11i = m10r*u01i + m10i*u01r + m11r*u11i + m11i*u11r;
        u00r = n00r; u00i = n00i; u01r = n01r; u01i = n01i;
        u10r = n10r; u10i = n10i; u11r = n11r; u11i = n11i;
    }

    float A = (u00r*u00r + u00i*u00i) - (u10r*u10r + u10i*u10i);
    float C = (u00i*u01r - u00r*u01i) - (u10i*u11r - u10r*u11i);

    float w = head_w[q];
    g_coef[q * 2 + 0] = w * A;
    g_coef[q * 2 + 1] = w * C;
    if (q == 0) g_coef[4] = head_b[0];
}

// Streaming kernel, L2-direct loads: ld.global.cg skips L1 allocation and
// fills at 32B sector granularity. Every previous variant (L1 path / TMA)
// pulled 64B per row from DRAM for the 8B it needed; if that granule is an
// L1-path artifact, .cg halves mandatory DRAM traffic (33.6MB -> 16.8MB).
__global__ void __launch_bounds__(256)
vqc_main_kernel(const float* __restrict__ X, float* __restrict__ out, int B) {
    int b = blockIdx.x * blockDim.x + threadIdx.x;
    if (b >= B) return;

    const float* p = X + (size_t)b * N_QUBITS;
    float x0, x1;
    asm volatile("ld.global.cg.v2.f32 {%0, %1}, [%2];"
                 : "=f"(x0), "=f"(x1) : "l"(p));

    float ka0 = g_coef[0], kc0 = g_coef[1];
    float ka1 = g_coef[2], kc1 = g_coef[3];
    float bias = g_coef[4];

    float s0, c0, s1, c1;
    __sincosf(x0, &s0, &c0);
    __sincosf(x1, &s1, &c1);

    out[b] = fmaf(ka0, c0, fmaf(-kc0, s0, fmaf(ka1, c1, fmaf(-kc1, s1, bias))));
}

extern "C" void kernel_launch(void* const* d_in, const int* in_sizes, int n_in,
                              void* d_out, int out_size) {
    const float* X      = (const float*)d_in[0];   // [B, 16]
    const float* params = (const float*)d_in[1];   // [8, 16, 3]
    const float* head_w = (const float*)d_in[2];   // [1, 2]
    const float* head_b = (const float*)d_in[3];   // [1]
    float* out = (float*)d_out;

    int B = in_sizes[0] / N_QUBITS;

    vqc_precompute_kernel<<<1, 32>>>(params, head_w, head_b);
    vqc_main_kernel<<<(B + 255) / 256, 256>>>(X, out, B);
}